// round 1
// baseline (speedup 1.0000x reference)
#include <cuda_runtime.h>
#include <math.h>

#define NN 100000
#define EE 1600000
#define FIN0 128
#define HID 64
#define KORD 14
#define HEADS 8
#define NGRAPH 128
#define NCLS 10

// ---------------- scratch (device globals; no runtime alloc) ----------------
__device__ float g_y  [NN * HID];
__device__ float g_t1 [NN * HID];
__device__ float g_t2 [NN * HID];
__device__ float g_out[NN * HID];
__device__ float g_h  [NN * HID];
__device__ int   g_deg[NN];
__device__ float g_dinv[NN];
__device__ int   g_rowptr[NN + 1];
__device__ int   g_cursor[NN];
__device__ int   g_cols[EE];
__device__ float g_wts[EE];
__device__ float g_coeff[KORD];

// ---------------- CSR build ----------------
__global__ void count_deg_kernel(const int* __restrict__ row) {
    int e = blockIdx.x * blockDim.x + threadIdx.x;
    if (e < EE) atomicAdd(&g_deg[row[e]], 1);
}

__global__ void dinv_kernel() {
    int i = blockIdx.x * blockDim.x + threadIdx.x;
    if (i < NN) {
        float d = (float)g_deg[i];
        g_dinv[i] = rsqrtf(fmaxf(d, 1.0f));
    }
}

// single-block exclusive scan of g_deg -> g_rowptr (N=100000, 1024 threads, ~98 items each)
__global__ void scan_kernel() {
    __shared__ int sums[1024];
    const int T = 1024;
    int tid = threadIdx.x;
    int per = (NN + T - 1) / T;
    int start = tid * per;
    int end = start + per; if (end > NN) end = NN;
    int local = 0;
    for (int i = start; i < end; i++) local += g_deg[i];
    sums[tid] = local;
    __syncthreads();
    for (int off = 1; off < T; off <<= 1) {
        int t = (tid >= off) ? sums[tid - off] : 0;
        __syncthreads();
        sums[tid] += t;
        __syncthreads();
    }
    int excl = sums[tid] - local;
    int run = excl;
    for (int i = start; i < end; i++) { g_rowptr[i] = run; run += g_deg[i]; }
    if (tid == T - 1) g_rowptr[NN] = run;
}

__global__ void scatter_kernel(const int* __restrict__ row, const int* __restrict__ col) {
    int e = blockIdx.x * blockDim.x + threadIdx.x;
    if (e < EE) {
        int r = row[e], c = col[e];
        int pos = g_rowptr[r] + atomicAdd(&g_cursor[r], 1);
        g_cols[pos] = c;
        g_wts[pos] = -g_dinv[r] * g_dinv[c];   // fold sign of L~ = -D^-1/2 A D^-1/2
    }
}

// ---------------- per-layer coeff = mean over heads ----------------
__global__ void coeff_kernel(const float* __restrict__ theta) {
    int k = threadIdx.x;
    if (k < KORD) {
        float s = 0.f;
        for (int h = 0; h < HEADS; h++) s += theta[h * KORD + k];
        g_coeff[k] = s * (1.0f / HEADS);
    }
}

// ---------------- GEMM: Y[N][64] = A[N][FIN] @ W[FIN][64] ----------------
template <int FIN>
__global__ __launch_bounds__(256) void gemm_kernel(const float* __restrict__ A,
                                                   const float* __restrict__ W,
                                                   float* __restrict__ Y) {
    __shared__ float As[64][68];   // transposed: As[k][r], padded stride keeps float4 align
    __shared__ float Ws[64][64];   // Ws[k][f]
    int rowbase = blockIdx.x * 64;
    int tid = threadIdx.x;
    int tx = tid & 15;   // col group: cols tx*4..tx*4+3
    int ty = tid >> 4;   // row group: rows ty*4..ty*4+3
    float acc[4][4];
#pragma unroll
    for (int i = 0; i < 4; i++)
#pragma unroll
        for (int j = 0; j < 4; j++) acc[i][j] = 0.f;

    for (int kk = 0; kk < FIN; kk += 64) {
        // stage A chunk (64 rows x 64 k), transposed into As[k][r]
#pragma unroll
        for (int j = 0; j < 4; j++) {
            int idx = tid + j * 256;      // 0..1023
            int r = idx >> 4;             // 0..63
            int kq = idx & 15;            // 0..15
            float4 v = make_float4(0.f, 0.f, 0.f, 0.f);
            int gr = rowbase + r;
            if (gr < NN) v = *(const float4*)(A + (size_t)gr * FIN + kk + kq * 4);
            As[kq * 4 + 0][r] = v.x;
            As[kq * 4 + 1][r] = v.y;
            As[kq * 4 + 2][r] = v.z;
            As[kq * 4 + 3][r] = v.w;
        }
        // stage W chunk
#pragma unroll
        for (int j = 0; j < 4; j++) {
            int idx = tid + j * 256;
            int k = idx >> 4;
            int fq = idx & 15;
            *(float4*)&Ws[k][fq * 4] = *(const float4*)(W + (size_t)(kk + k) * 64 + fq * 4);
        }
        __syncthreads();
#pragma unroll
        for (int k = 0; k < 64; k++) {
            float4 a = *(const float4*)&As[k][ty * 4];
            float4 b = *(const float4*)&Ws[k][tx * 4];
            float ar[4] = {a.x, a.y, a.z, a.w};
            float br[4] = {b.x, b.y, b.z, b.w};
#pragma unroll
            for (int i = 0; i < 4; i++)
#pragma unroll
                for (int j = 0; j < 4; j++) acc[i][j] += ar[i] * br[j];
        }
        __syncthreads();
    }
#pragma unroll
    for (int i = 0; i < 4; i++) {
        int r = rowbase + ty * 4 + i;
        if (r < NN) {
            float4 v = make_float4(acc[i][0], acc[i][1], acc[i][2], acc[i][3]);
            *(float4*)&Y[(size_t)r * HID + tx * 4] = v;
        }
    }
}

// ---------------- Chebyshev propagation (warp per row, float2 per lane) ----------------
__device__ __forceinline__ float2 prop_row(const float2* __restrict__ tc2, int row, int lane) {
    int s = g_rowptr[row];
    int e = g_rowptr[row + 1];
    float2 acc0 = make_float2(0.f, 0.f), acc1 = make_float2(0.f, 0.f);
    int i = s;
    for (; i + 1 < e; i += 2) {
        int   c0 = __ldg(&g_cols[i]);
        int   c1 = __ldg(&g_cols[i + 1]);
        float w0 = __ldg(&g_wts[i]);
        float w1 = __ldg(&g_wts[i + 1]);
        float2 v0 = __ldg(&tc2[(size_t)c0 * 32 + lane]);
        float2 v1 = __ldg(&tc2[(size_t)c1 * 32 + lane]);
        acc0.x += w0 * v0.x; acc0.y += w0 * v0.y;
        acc1.x += w1 * v1.x; acc1.y += w1 * v1.y;
    }
    if (i < e) {
        int   c0 = __ldg(&g_cols[i]);
        float w0 = __ldg(&g_wts[i]);
        float2 v0 = __ldg(&tc2[(size_t)c0 * 32 + lane]);
        acc0.x += w0 * v0.x; acc0.y += w0 * v0.y;
    }
    return make_float2(acc0.x + acc1.x, acc0.y + acc1.y);
}

// first: t_cur = L~ y ; out = c0*y + c1*t_cur
__global__ __launch_bounds__(256) void cheb_first_kernel(const float* __restrict__ y,
                                                         float* __restrict__ tcur,
                                                         float* __restrict__ outb) {
    int row = blockIdx.x * 8 + (threadIdx.x >> 5);
    int lane = threadIdx.x & 31;
    if (row >= NN) return;
    float2 acc = prop_row((const float2*)y, row, lane);
    float c0 = g_coeff[0], c1 = g_coeff[1];
    size_t idx = (size_t)row * 32 + lane;
    float2 yv = ((const float2*)y)[idx];
    ((float2*)tcur)[idx] = acc;
    ((float2*)outb)[idx] = make_float2(c0 * yv.x + c1 * acc.x, c0 * yv.y + c1 * acc.y);
}

// step k: t_next = 2*L~ t_cur - t_prev ; out += c_k * t_next
__global__ __launch_bounds__(256) void cheb_step_kernel(const float* __restrict__ tcur,
                                                        const float* __restrict__ tprev,
                                                        float* __restrict__ tnext,
                                                        float* __restrict__ outb, int k) {
    int row = blockIdx.x * 8 + (threadIdx.x >> 5);
    int lane = threadIdx.x & 31;
    if (row >= NN) return;
    float2 acc = prop_row((const float2*)tcur, row, lane);
    size_t idx = (size_t)row * 32 + lane;
    float2 p = ((const float2*)tprev)[idx];
    float2 tn = make_float2(2.f * acc.x - p.x, 2.f * acc.y - p.y);
    ((float2*)tnext)[idx] = tn;
    float ck = g_coeff[k];
    float2 o = ((float2*)outb)[idx];
    o.x += ck * tn.x; o.y += ck * tn.y;
    ((float2*)outb)[idx] = o;
}

// last step k=K-1: h_out = relu(out + c_k*(2*L~ t_cur - t_prev) + bias)
__global__ __launch_bounds__(256) void cheb_last_kernel(const float* __restrict__ tcur,
                                                        const float* __restrict__ tprev,
                                                        const float* __restrict__ outb,
                                                        const float* __restrict__ bias,
                                                        float* __restrict__ hout, int k) {
    int row = blockIdx.x * 8 + (threadIdx.x >> 5);
    int lane = threadIdx.x & 31;
    if (row >= NN) return;
    float2 acc = prop_row((const float2*)tcur, row, lane);
    size_t idx = (size_t)row * 32 + lane;
    float2 p = ((const float2*)tprev)[idx];
    float2 tn = make_float2(2.f * acc.x - p.x, 2.f * acc.y - p.y);
    float ck = g_coeff[k];
    float2 o = ((const float2*)outb)[idx];
    float b0 = bias[2 * lane], b1 = bias[2 * lane + 1];
    float r0 = fmaxf(o.x + ck * tn.x + b0, 0.f);
    float r1 = fmaxf(o.y + ck * tn.y + b1, 0.f);
    ((float2*)hout)[idx] = make_float2(r0, r1);
}

// ---------------- pool (segment mean over sorted batch) + MLP head + log_softmax ----------------
__global__ __launch_bounds__(256) void pool_head_kernel(const float* __restrict__ h,
                                                        const int* __restrict__ batch,
                                                        const float* __restrict__ lin1w,
                                                        const float* __restrict__ lin1b,
                                                        const float* __restrict__ lin2w,
                                                        const float* __restrict__ lin2b,
                                                        float* __restrict__ out) {
    int g = blockIdx.x;
    int tid = threadIdx.x;
    // binary search for [start, end) of this graph in sorted batch
    int lo = 0, hi = NN;
    while (lo < hi) { int m = (lo + hi) >> 1; if (batch[m] < g) lo = m + 1; else hi = m; }
    int start = lo;
    lo = start; hi = NN;
    while (lo < hi) { int m = (lo + hi) >> 1; if (batch[m] < g + 1) lo = m + 1; else hi = m; }
    int end = lo;

    int f = tid & 63, sub = tid >> 6;      // 4 node-strided partial sums per feature
    float acc = 0.f;
    for (int i = start + sub; i < end; i += 4) acc += h[(size_t)i * HID + f];
    __shared__ float red[4][64];
    red[sub][f] = acc;
    __syncthreads();
    __shared__ float pooled[64];
    if (tid < 64) {
        float s = red[0][tid] + red[1][tid] + red[2][tid] + red[3][tid];
        float cnt = (float)(end - start);
        pooled[tid] = s / fmaxf(cnt, 1.0f);
    }
    __syncthreads();
    __shared__ float g1[64];
    if (tid < 64) {
        float a = lin1b[tid];
        for (int fk = 0; fk < 64; fk++) a += pooled[fk] * lin1w[fk * 64 + tid];
        g1[tid] = fmaxf(a, 0.f);
    }
    __syncthreads();
    __shared__ float logits[NCLS];
    if (tid < NCLS) {
        float a = lin2b[tid];
        for (int fk = 0; fk < 64; fk++) a += g1[fk] * lin2w[fk * NCLS + tid];
        logits[tid] = a;
    }
    __syncthreads();
    __shared__ float s_lse;
    if (tid == 0) {
        float mx = logits[0];
        for (int c = 1; c < NCLS; c++) mx = fmaxf(mx, logits[c]);
        float s = 0.f;
        for (int c = 0; c < NCLS; c++) s += expf(logits[c] - mx);
        s_lse = mx + logf(s);
    }
    __syncthreads();
    if (tid < NCLS) out[g * NCLS + tid] = logits[tid] - s_lse;
}

// ---------------- host orchestration ----------------
static void spectral_layer(const float* hin, int fin,
                           const float* W, const float* theta, const float* bias,
                           float* p_y, float* p_t1, float* p_t2, float* p_out, float* hout) {
    const int CHEB_GRID = (NN + 7) / 8;
    coeff_kernel<<<1, 32>>>(theta);
    if (fin == 128)
        gemm_kernel<128><<<(NN + 63) / 64, 256>>>(hin, W, p_y);
    else
        gemm_kernel<64><<<(NN + 63) / 64, 256>>>(hin, W, p_y);
    cheb_first_kernel<<<CHEB_GRID, 256>>>(p_y, p_t1, p_out);
    float* tp = p_y; float* tc = p_t1; float* tn = p_t2;
    for (int k = 2; k <= KORD - 2; k++) {
        cheb_step_kernel<<<CHEB_GRID, 256>>>(tc, tp, tn, p_out, k);
        float* tmp = tp; tp = tc; tc = tn; tn = tmp;
    }
    cheb_last_kernel<<<CHEB_GRID, 256>>>(tc, tp, p_out, bias, hout, KORD - 1);
}

extern "C" void kernel_launch(void* const* d_in, const int* in_sizes, int n_in,
                              void* d_out, int out_size) {
    const float* x      = (const float*)d_in[0];
    const int*   ei     = (const int*)d_in[1];
    const int*   batch  = (const int*)d_in[2];
    const float* W1     = (const float*)d_in[3];
    const float* theta1 = (const float*)d_in[4];
    const float* b1     = (const float*)d_in[5];
    const float* Ws     = (const float*)d_in[6];
    const float* thetas = (const float*)d_in[7];
    const float* bs     = (const float*)d_in[8];
    const float* lin1w  = (const float*)d_in[9];
    const float* lin1b  = (const float*)d_in[10];
    const float* lin2w  = (const float*)d_in[11];
    const float* lin2b  = (const float*)d_in[12];
    float* out = (float*)d_out;

    const int* row = ei;
    const int* col = ei + EE;

    void *pv;
    float *p_y, *p_t1, *p_t2, *p_out, *p_h;
    int *p_deg, *p_cur;
    cudaGetSymbolAddress(&pv, g_y);    p_y   = (float*)pv;
    cudaGetSymbolAddress(&pv, g_t1);   p_t1  = (float*)pv;
    cudaGetSymbolAddress(&pv, g_t2);   p_t2  = (float*)pv;
    cudaGetSymbolAddress(&pv, g_out);  p_out = (float*)pv;
    cudaGetSymbolAddress(&pv, g_h);    p_h   = (float*)pv;
    cudaGetSymbolAddress(&pv, g_deg);  p_deg = (int*)pv;
    cudaGetSymbolAddress(&pv, g_cursor); p_cur = (int*)pv;

    // ---- CSR build with edge weights ----
    cudaMemsetAsync(p_deg, 0, NN * sizeof(int));
    count_deg_kernel<<<(EE + 255) / 256, 256>>>(row);
    dinv_kernel<<<(NN + 255) / 256, 256>>>();
    scan_kernel<<<1, 1024>>>();
    cudaMemsetAsync(p_cur, 0, NN * sizeof(int));
    scatter_kernel<<<(EE + 255) / 256, 256>>>(row, col);

    // ---- 3 spectral layers ----
    spectral_layer(x,   128, W1, theta1, b1, p_y, p_t1, p_t2, p_out, p_h);
    spectral_layer(p_h,  64, Ws,              thetas,           bs,
                   p_y, p_t1, p_t2, p_out, p_h);
    spectral_layer(p_h,  64, Ws + 64 * 64,    thetas + HEADS * KORD, bs + HID,
                   p_y, p_t1, p_t2, p_out, p_h);

    // ---- pool + head ----
    pool_head_kernel<<<NGRAPH, 256>>>(p_h, batch, lin1w, lin1b, lin2w, lin2b, out);
}

// round 2
// speedup vs baseline: 1.0940x; 1.0940x over previous
#include <cuda_runtime.h>
#include <cuda_fp16.h>
#include <math.h>

#define NN 100000
#define EE 1600000
#define HID 64
#define KORD 14
#define HEADS 8
#define NGRAPH 128
#define NCLS 10

// ---------------- scratch (device globals; no runtime alloc) ----------------
__device__ __half g_yh [NN * HID];   // Chebyshev T buffers (half storage)
__device__ __half g_t1h[NN * HID];
__device__ __half g_t2h[NN * HID];
__device__ float  g_out[NN * HID];   // fp32 accumulator of sum_k c_k T_k
__device__ float  g_h  [NN * HID];   // fp32 layer output (GEMM input / pool input)
__device__ int    g_deg[NN];
__device__ float  g_dinv[NN];
__device__ int    g_rowptr[NN + 1];
__device__ int    g_cursor[NN];
__device__ int2   g_edge[EE];        // {col, float_bits(weight)}
__device__ float  g_coeff[KORD];

// ---------------- CSR build ----------------
__global__ void count_deg_kernel(const int* __restrict__ row) {
    int e = blockIdx.x * blockDim.x + threadIdx.x;
    if (e < EE) atomicAdd(&g_deg[row[e]], 1);
}

__global__ void dinv_kernel() {
    int i = blockIdx.x * blockDim.x + threadIdx.x;
    if (i < NN) {
        float d = (float)g_deg[i];
        g_dinv[i] = rsqrtf(fmaxf(d, 1.0f));
    }
}

// single-block exclusive scan of g_deg -> g_rowptr
__global__ void scan_kernel() {
    __shared__ int sums[1024];
    const int T = 1024;
    int tid = threadIdx.x;
    int per = (NN + T - 1) / T;
    int start = tid * per;
    int end = start + per; if (end > NN) end = NN;
    int local = 0;
    for (int i = start; i < end; i++) local += g_deg[i];
    sums[tid] = local;
    __syncthreads();
    for (int off = 1; off < T; off <<= 1) {
        int t = (tid >= off) ? sums[tid - off] : 0;
        __syncthreads();
        sums[tid] += t;
        __syncthreads();
    }
    int excl = sums[tid] - local;
    int run = excl;
    for (int i = start; i < end; i++) { g_rowptr[i] = run; run += g_deg[i]; }
    if (tid == T - 1) g_rowptr[NN] = run;
}

__global__ void scatter_kernel(const int* __restrict__ row, const int* __restrict__ col) {
    int e = blockIdx.x * blockDim.x + threadIdx.x;
    if (e < EE) {
        int r = row[e], c = col[e];
        int pos = g_rowptr[r] + atomicAdd(&g_cursor[r], 1);
        float w = -g_dinv[r] * g_dinv[c];   // fold sign of L~ = -D^-1/2 A D^-1/2
        g_edge[pos] = make_int2(c, __float_as_int(w));
    }
}

// ---------------- per-layer coeff = mean over heads ----------------
__global__ void coeff_kernel(const float* __restrict__ theta) {
    int k = threadIdx.x;
    if (k < KORD) {
        float s = 0.f;
        for (int h = 0; h < HEADS; h++) s += theta[h * KORD + k];
        g_coeff[k] = s * (1.0f / HEADS);
    }
}

// ---------------- GEMM: Yh[N][64] = A[N][FIN] @ W[FIN][64]  (half output) ----------------
template <int FIN>
__global__ __launch_bounds__(256) void gemm_kernel(const float* __restrict__ A,
                                                   const float* __restrict__ W,
                                                   __half* __restrict__ Yh) {
    __shared__ float As[64][68];
    __shared__ float Ws[64][64];
    int rowbase = blockIdx.x * 64;
    int tid = threadIdx.x;
    int tx = tid & 15;
    int ty = tid >> 4;
    float acc[4][4];
#pragma unroll
    for (int i = 0; i < 4; i++)
#pragma unroll
        for (int j = 0; j < 4; j++) acc[i][j] = 0.f;

    for (int kk = 0; kk < FIN; kk += 64) {
#pragma unroll
        for (int j = 0; j < 4; j++) {
            int idx = tid + j * 256;
            int r = idx >> 4;
            int kq = idx & 15;
            float4 v = make_float4(0.f, 0.f, 0.f, 0.f);
            int gr = rowbase + r;
            if (gr < NN) v = *(const float4*)(A + (size_t)gr * FIN + kk + kq * 4);
            As[kq * 4 + 0][r] = v.x;
            As[kq * 4 + 1][r] = v.y;
            As[kq * 4 + 2][r] = v.z;
            As[kq * 4 + 3][r] = v.w;
        }
#pragma unroll
        for (int j = 0; j < 4; j++) {
            int idx = tid + j * 256;
            int k = idx >> 4;
            int fq = idx & 15;
            *(float4*)&Ws[k][fq * 4] = *(const float4*)(W + (size_t)(kk + k) * 64 + fq * 4);
        }
        __syncthreads();
#pragma unroll
        for (int k = 0; k < 64; k++) {
            float4 a = *(const float4*)&As[k][ty * 4];
            float4 b = *(const float4*)&Ws[k][tx * 4];
            float ar[4] = {a.x, a.y, a.z, a.w};
            float br[4] = {b.x, b.y, b.z, b.w};
#pragma unroll
            for (int i = 0; i < 4; i++)
#pragma unroll
                for (int j = 0; j < 4; j++) acc[i][j] += ar[i] * br[j];
        }
        __syncthreads();
    }
#pragma unroll
    for (int i = 0; i < 4; i++) {
        int r = rowbase + ty * 4 + i;
        if (r < NN) {
            __half2* dst = (__half2*)(Yh + (size_t)r * HID + tx * 4);
            dst[0] = __floats2half2_rn(acc[i][0], acc[i][1]);
            dst[1] = __floats2half2_rn(acc[i][2], acc[i][3]);
        }
    }
}

// ---------------- Chebyshev propagation (warp per row, half2 per lane) ----------------
__device__ __forceinline__ float2 prop_row(const __half2* __restrict__ t, int row, int lane) {
    int s = g_rowptr[row];
    int e = g_rowptr[row + 1];
    float ax = 0.f, ay = 0.f;
    for (int base = s; base < e; base += 32) {
        int idx = base + lane;
        int2 ew = make_int2(0, 0);
        if (idx < e) ew = __ldg(&g_edge[idx]);
        int cnt = e - base; if (cnt > 32) cnt = 32;
#pragma unroll 4
        for (int j = 0; j < cnt; j++) {
            int   cj = __shfl_sync(0xffffffffu, ew.x, j);
            float wj = __int_as_float(__shfl_sync(0xffffffffu, ew.y, j));
            float2 v = __half22float2(__ldg(&t[(size_t)cj * 32 + lane]));
            ax += wj * v.x;
            ay += wj * v.y;
        }
    }
    return make_float2(ax, ay);
}

// first: t_cur = L~ y ; out = c0*y + c1*t_cur
__global__ __launch_bounds__(256) void cheb_first_kernel(const __half* __restrict__ yh,
                                                         __half* __restrict__ tcur,
                                                         float* __restrict__ outb) {
    int row = blockIdx.x * 8 + (threadIdx.x >> 5);
    int lane = threadIdx.x & 31;
    if (row >= NN) return;
    float2 acc = prop_row((const __half2*)yh, row, lane);
    float c0 = g_coeff[0], c1 = g_coeff[1];
    size_t idx = (size_t)row * 32 + lane;
    float2 yv = __half22float2(((const __half2*)yh)[idx]);
    ((__half2*)tcur)[idx] = __floats2half2_rn(acc.x, acc.y);
    ((float2*)outb)[idx] = make_float2(c0 * yv.x + c1 * acc.x, c0 * yv.y + c1 * acc.y);
}

// step k: t_next = 2*L~ t_cur - t_prev ; out += c_k * t_next
__global__ __launch_bounds__(256) void cheb_step_kernel(const __half* __restrict__ tcur,
                                                        const __half* __restrict__ tprev,
                                                        __half* __restrict__ tnext,
                                                        float* __restrict__ outb, int k) {
    int row = blockIdx.x * 8 + (threadIdx.x >> 5);
    int lane = threadIdx.x & 31;
    if (row >= NN) return;
    float2 acc = prop_row((const __half2*)tcur, row, lane);
    size_t idx = (size_t)row * 32 + lane;
    float2 p = __half22float2(((const __half2*)tprev)[idx]);
    float2 tn = make_float2(2.f * acc.x - p.x, 2.f * acc.y - p.y);
    ((__half2*)tnext)[idx] = __floats2half2_rn(tn.x, tn.y);
    float ck = g_coeff[k];
    float2 o = ((float2*)outb)[idx];
    o.x += ck * tn.x; o.y += ck * tn.y;
    ((float2*)outb)[idx] = o;
}

// last step: h_out = relu(out + c_k*(2*L~ t_cur - t_prev) + bias)
__global__ __launch_bounds__(256) void cheb_last_kernel(const __half* __restrict__ tcur,
                                                        const __half* __restrict__ tprev,
                                                        const float* __restrict__ outb,
                                                        const float* __restrict__ bias,
                                                        float* __restrict__ hout, int k) {
    int row = blockIdx.x * 8 + (threadIdx.x >> 5);
    int lane = threadIdx.x & 31;
    if (row >= NN) return;
    float2 acc = prop_row((const __half2*)tcur, row, lane);
    size_t idx = (size_t)row * 32 + lane;
    float2 p = __half22float2(((const __half2*)tprev)[idx]);
    float2 tn = make_float2(2.f * acc.x - p.x, 2.f * acc.y - p.y);
    float ck = g_coeff[k];
    float2 o = ((const float2*)outb)[idx];
    float b0 = bias[2 * lane], b1 = bias[2 * lane + 1];
    float r0 = fmaxf(o.x + ck * tn.x + b0, 0.f);
    float r1 = fmaxf(o.y + ck * tn.y + b1, 0.f);
    ((float2*)hout)[idx] = make_float2(r0, r1);
}

// ---------------- pool + head + log_softmax ----------------
__global__ __launch_bounds__(256) void pool_head_kernel(const float* __restrict__ h,
                                                        const int* __restrict__ batch,
                                                        const float* __restrict__ lin1w,
                                                        const float* __restrict__ lin1b,
                                                        const float* __restrict__ lin2w,
                                                        const float* __restrict__ lin2b,
                                                        float* __restrict__ out) {
    int g = blockIdx.x;
    int tid = threadIdx.x;
    int lo = 0, hi = NN;
    while (lo < hi) { int m = (lo + hi) >> 1; if (batch[m] < g) lo = m + 1; else hi = m; }
    int start = lo;
    lo = start; hi = NN;
    while (lo < hi) { int m = (lo + hi) >> 1; if (batch[m] < g + 1) lo = m + 1; else hi = m; }
    int end = lo;

    int f = tid & 63, sub = tid >> 6;
    float acc = 0.f;
    for (int i = start + sub; i < end; i += 4) acc += h[(size_t)i * HID + f];
    __shared__ float red[4][64];
    red[sub][f] = acc;
    __syncthreads();
    __shared__ float pooled[64];
    if (tid < 64) {
        float s = red[0][tid] + red[1][tid] + red[2][tid] + red[3][tid];
        float cnt = (float)(end - start);
        pooled[tid] = s / fmaxf(cnt, 1.0f);
    }
    __syncthreads();
    __shared__ float g1[64];
    if (tid < 64) {
        float a = lin1b[tid];
        for (int fk = 0; fk < 64; fk++) a += pooled[fk] * lin1w[fk * 64 + tid];
        g1[tid] = fmaxf(a, 0.f);
    }
    __syncthreads();
    __shared__ float logits[NCLS];
    if (tid < NCLS) {
        float a = lin2b[tid];
        for (int fk = 0; fk < 64; fk++) a += g1[fk] * lin2w[fk * NCLS + tid];
        logits[tid] = a;
    }
    __syncthreads();
    __shared__ float s_lse;
    if (tid == 0) {
        float mx = logits[0];
        for (int c = 1; c < NCLS; c++) mx = fmaxf(mx, logits[c]);
        float s = 0.f;
        for (int c = 0; c < NCLS; c++) s += expf(logits[c] - mx);
        s_lse = mx + logf(s);
    }
    __syncthreads();
    if (tid < NCLS) out[g * NCLS + tid] = logits[tid] - s_lse;
}

// ---------------- host orchestration ----------------
static void spectral_layer(const float* hin, int fin,
                           const float* W, const float* theta, const float* bias,
                           __half* p_yh, __half* p_t1h, __half* p_t2h,
                           float* p_out, float* hout) {
    const int CHEB_GRID = (NN + 7) / 8;
    coeff_kernel<<<1, 32>>>(theta);
    if (fin == 128)
        gemm_kernel<128><<<(NN + 63) / 64, 256>>>(hin, W, p_yh);
    else
        gemm_kernel<64><<<(NN + 63) / 64, 256>>>(hin, W, p_yh);
    cheb_first_kernel<<<CHEB_GRID, 256>>>(p_yh, p_t1h, p_out);
    __half* tp = p_yh; __half* tc = p_t1h; __half* tn = p_t2h;
    for (int k = 2; k <= KORD - 2; k++) {
        cheb_step_kernel<<<CHEB_GRID, 256>>>(tc, tp, tn, p_out, k);
        __half* tmp = tp; tp = tc; tc = tn; tn = tmp;
    }
    cheb_last_kernel<<<CHEB_GRID, 256>>>(tc, tp, p_out, bias, hout, KORD - 1);
}

extern "C" void kernel_launch(void* const* d_in, const int* in_sizes, int n_in,
                              void* d_out, int out_size) {
    const float* x      = (const float*)d_in[0];
    const int*   ei     = (const int*)d_in[1];
    const int*   batch  = (const int*)d_in[2];
    const float* W1     = (const float*)d_in[3];
    const float* theta1 = (const float*)d_in[4];
    const float* b1     = (const float*)d_in[5];
    const float* Ws     = (const float*)d_in[6];
    const float* thetas = (const float*)d_in[7];
    const float* bs     = (const float*)d_in[8];
    const float* lin1w  = (const float*)d_in[9];
    const float* lin1b  = (const float*)d_in[10];
    const float* lin2w  = (const float*)d_in[11];
    const float* lin2b  = (const float*)d_in[12];
    float* out = (float*)d_out;

    const int* row = ei;
    const int* col = ei + EE;

    void *pv;
    __half *p_yh, *p_t1h, *p_t2h;
    float *p_out, *p_h;
    int *p_deg, *p_cur;
    cudaGetSymbolAddress(&pv, g_yh);   p_yh  = (__half*)pv;
    cudaGetSymbolAddress(&pv, g_t1h);  p_t1h = (__half*)pv;
    cudaGetSymbolAddress(&pv, g_t2h);  p_t2h = (__half*)pv;
    cudaGetSymbolAddress(&pv, g_out);  p_out = (float*)pv;
    cudaGetSymbolAddress(&pv, g_h);    p_h   = (float*)pv;
    cudaGetSymbolAddress(&pv, g_deg);  p_deg = (int*)pv;
    cudaGetSymbolAddress(&pv, g_cursor); p_cur = (int*)pv;

    // ---- CSR build with edge weights ----
    cudaMemsetAsync(p_deg, 0, NN * sizeof(int));
    count_deg_kernel<<<(EE + 255) / 256, 256>>>(row);
    dinv_kernel<<<(NN + 255) / 256, 256>>>();
    scan_kernel<<<1, 1024>>>();
    cudaMemsetAsync(p_cur, 0, NN * sizeof(int));
    scatter_kernel<<<(EE + 255) / 256, 256>>>(row, col);

    // ---- 3 spectral layers ----
    spectral_layer(x,   128, W1, theta1, b1, p_yh, p_t1h, p_t2h, p_out, p_h);
    spectral_layer(p_h,  64, Ws,           thetas,                bs,
                   p_yh, p_t1h, p_t2h, p_out, p_h);
    spectral_layer(p_h,  64, Ws + 64 * 64, thetas + HEADS * KORD, bs + HID,
                   p_yh, p_t1h, p_t2h, p_out, p_h);

    // ---- pool + head ----
    pool_head_kernel<<<NGRAPH, 256>>>(p_h, batch, lin1w, lin1b, lin2w, lin2b, out);
}

// round 3
// speedup vs baseline: 1.1610x; 1.0612x over previous
#include <cuda_runtime.h>
#include <cuda_fp16.h>
#include <math.h>

#define NN 100000
#define EE 1600000
#define HID 64
#define KORD 14
#define HEADS 8
#define NGRAPH 128
#define NCLS 10

// ---------------- scratch (device globals; no runtime alloc) ----------------
__device__ __half g_yh  [NN * HID];   // Chebyshev T buffers (half storage)
__device__ __half g_t1h [NN * HID];
__device__ __half g_t2h [NN * HID];
__device__ __half g_outh[NN * HID];   // half accumulator of sum_k c_k T_k
__device__ float  g_h   [NN * HID];   // fp32 layer output (GEMM input / pool input)
__device__ int    g_deg[NN];
__device__ float  g_dinv[NN];
__device__ int    g_rowptr[NN + 1];
__device__ int    g_cursor[NN];
__device__ int2   g_edge[EE];         // {col, float_bits(weight)}
__device__ float  g_coeff[3][KORD];

// ---------------- CSR build ----------------
__global__ void count_deg_kernel(const int* __restrict__ row) {
    int e = blockIdx.x * blockDim.x + threadIdx.x;
    if (e < EE) atomicAdd(&g_deg[row[e]], 1);
}

__global__ void dinv_kernel() {
    int i = blockIdx.x * blockDim.x + threadIdx.x;
    if (i < NN) {
        float d = (float)g_deg[i];
        g_dinv[i] = rsqrtf(fmaxf(d, 1.0f));
    }
}

// single-block exclusive scan of g_deg -> g_rowptr
__global__ void scan_kernel() {
    __shared__ int sums[1024];
    const int T = 1024;
    int tid = threadIdx.x;
    int per = (NN + T - 1) / T;
    int start = tid * per;
    int end = start + per; if (end > NN) end = NN;
    int local = 0;
    for (int i = start; i < end; i++) local += g_deg[i];
    sums[tid] = local;
    __syncthreads();
    for (int off = 1; off < T; off <<= 1) {
        int t = (tid >= off) ? sums[tid - off] : 0;
        __syncthreads();
        sums[tid] += t;
        __syncthreads();
    }
    int excl = sums[tid] - local;
    int run = excl;
    for (int i = start; i < end; i++) { g_rowptr[i] = run; run += g_deg[i]; }
    if (tid == T - 1) g_rowptr[NN] = run;
}

__global__ void scatter_kernel(const int* __restrict__ row, const int* __restrict__ col) {
    int e = blockIdx.x * blockDim.x + threadIdx.x;
    if (e < EE) {
        int r = row[e], c = col[e];
        int pos = g_rowptr[r] + atomicAdd(&g_cursor[r], 1);
        float w = -g_dinv[r] * g_dinv[c];   // fold sign of L~ = -D^-1/2 A D^-1/2
        g_edge[pos] = make_int2(c, __float_as_int(w));
    }
}

// ---------------- all-layer coeff = mean over heads ----------------
__global__ void coeff_kernel(const float* __restrict__ theta1,
                             const float* __restrict__ thetas) {
    int t = threadIdx.x;              // 0..3*KORD-1
    if (t < 3 * KORD) {
        int layer = t / KORD, k = t % KORD;
        const float* th = (layer == 0) ? theta1 : thetas + (layer - 1) * HEADS * KORD;
        float s = 0.f;
        for (int h = 0; h < HEADS; h++) s += th[h * KORD + k];
        g_coeff[layer][k] = s * (1.0f / HEADS);
    }
}

// ---------------- GEMM: Yh[N][64] = A[N][FIN] @ W[FIN][64]  (half output) ----------------
template <int FIN>
__global__ __launch_bounds__(256) void gemm_kernel(const float* __restrict__ A,
                                                   const float* __restrict__ W,
                                                   __half* __restrict__ Yh) {
    __shared__ float As[64][68];
    __shared__ float Ws[64][64];
    int rowbase = blockIdx.x * 64;
    int tid = threadIdx.x;
    int tx = tid & 15;
    int ty = tid >> 4;
    float acc[4][4];
#pragma unroll
    for (int i = 0; i < 4; i++)
#pragma unroll
        for (int j = 0; j < 4; j++) acc[i][j] = 0.f;

    for (int kk = 0; kk < FIN; kk += 64) {
#pragma unroll
        for (int j = 0; j < 4; j++) {
            int idx = tid + j * 256;
            int r = idx >> 4;
            int kq = idx & 15;
            float4 v = make_float4(0.f, 0.f, 0.f, 0.f);
            int gr = rowbase + r;
            if (gr < NN) v = *(const float4*)(A + (size_t)gr * FIN + kk + kq * 4);
            As[kq * 4 + 0][r] = v.x;
            As[kq * 4 + 1][r] = v.y;
            As[kq * 4 + 2][r] = v.z;
            As[kq * 4 + 3][r] = v.w;
        }
#pragma unroll
        for (int j = 0; j < 4; j++) {
            int idx = tid + j * 256;
            int k = idx >> 4;
            int fq = idx & 15;
            *(float4*)&Ws[k][fq * 4] = *(const float4*)(W + (size_t)(kk + k) * 64 + fq * 4);
        }
        __syncthreads();
#pragma unroll
        for (int k = 0; k < 64; k++) {
            float4 a = *(const float4*)&As[k][ty * 4];
            float4 b = *(const float4*)&Ws[k][tx * 4];
            float ar[4] = {a.x, a.y, a.z, a.w};
            float br[4] = {b.x, b.y, b.z, b.w};
#pragma unroll
            for (int i = 0; i < 4; i++)
#pragma unroll
                for (int j = 0; j < 4; j++) acc[i][j] += ar[i] * br[j];
        }
        __syncthreads();
    }
#pragma unroll
    for (int i = 0; i < 4; i++) {
        int r = rowbase + ty * 4 + i;
        if (r < NN) {
            __half2* dst = (__half2*)(Yh + (size_t)r * HID + tx * 4);
            dst[0] = __floats2half2_rn(acc[i][0], acc[i][1]);
            dst[1] = __floats2half2_rn(acc[i][2], acc[i][3]);
        }
    }
}

// ---------------- Chebyshev propagation: half-warp per row, 4 features/lane ----------------
// t viewed as int2[NN*16] (each int2 = 4 halves). Returns 4 fp32 partials.
__device__ __forceinline__ float4 prop_row4(const int2* __restrict__ t,
                                            int s, int e, int sub, unsigned mask) {
    float ax = 0.f, ay = 0.f, az = 0.f, aw = 0.f;
    for (int base = s; base < e; base += 16) {
        int idx = base + sub;
        int2 ew = make_int2(0, 0);
        if (idx < e) ew = __ldg(&g_edge[idx]);
        int cnt = e - base; if (cnt > 16) cnt = 16;
#pragma unroll 8
        for (int j = 0; j < cnt; j++) {
            int   cj = __shfl_sync(mask, ew.x, j, 16);
            float wj = __int_as_float(__shfl_sync(mask, ew.y, j, 16));
            int2 raw = __ldg(&t[(size_t)cj * 16 + sub]);
            float2 f0 = __half22float2(*(__half2*)&raw.x);
            float2 f1 = __half22float2(*(__half2*)&raw.y);
            ax += wj * f0.x; ay += wj * f0.y;
            az += wj * f1.x; aw += wj * f1.y;
        }
    }
    return make_float4(ax, ay, az, aw);
}

__device__ __forceinline__ int2 pack4(float a, float b, float c, float d) {
    __half2 h0 = __floats2half2_rn(a, b);
    __half2 h1 = __floats2half2_rn(c, d);
    int2 r;
    r.x = *(int*)&h0;
    r.y = *(int*)&h1;
    return r;
}

__device__ __forceinline__ float4 unpack4(int2 raw) {
    float2 f0 = __half22float2(*(__half2*)&raw.x);
    float2 f1 = __half22float2(*(__half2*)&raw.y);
    return make_float4(f0.x, f0.y, f1.x, f1.y);
}

// first: t_cur = L~ y ; out = c0*y + c1*t_cur
__global__ __launch_bounds__(256) void cheb_first_kernel(const __half* __restrict__ yh,
                                                         __half* __restrict__ tcur,
                                                         __half* __restrict__ outb,
                                                         int layer) {
    int lane = threadIdx.x & 31;
    int half_id = lane >> 4;
    int sub = lane & 15;
    int row = blockIdx.x * 16 + ((threadIdx.x >> 5) << 1) + half_id;
    if (row >= NN) return;
    unsigned mask = 0xFFFFu << (half_id << 4);
    int s = g_rowptr[row], e = g_rowptr[row + 1];
    float4 acc = prop_row4((const int2*)yh, s, e, sub, mask);
    float c0 = g_coeff[layer][0], c1 = g_coeff[layer][1];
    size_t idx = (size_t)row * 16 + sub;
    float4 yv = unpack4(((const int2*)yh)[idx]);
    ((int2*)tcur)[idx] = pack4(acc.x, acc.y, acc.z, acc.w);
    ((int2*)outb)[idx] = pack4(c0 * yv.x + c1 * acc.x, c0 * yv.y + c1 * acc.y,
                               c0 * yv.z + c1 * acc.z, c0 * yv.w + c1 * acc.w);
}

// step k: t_next = 2*L~ t_cur - t_prev ; out += c_k * t_next
__global__ __launch_bounds__(256) void cheb_step_kernel(const __half* __restrict__ tcur,
                                                        const __half* __restrict__ tprev,
                                                        __half* __restrict__ tnext,
                                                        __half* __restrict__ outb,
                                                        int layer, int k) {
    int lane = threadIdx.x & 31;
    int half_id = lane >> 4;
    int sub = lane & 15;
    int row = blockIdx.x * 16 + ((threadIdx.x >> 5) << 1) + half_id;
    if (row >= NN) return;
    unsigned mask = 0xFFFFu << (half_id << 4);
    int s = g_rowptr[row], e = g_rowptr[row + 1];
    float4 acc = prop_row4((const int2*)tcur, s, e, sub, mask);
    size_t idx = (size_t)row * 16 + sub;
    float4 p = unpack4(((const int2*)tprev)[idx]);
    float4 tn = make_float4(2.f * acc.x - p.x, 2.f * acc.y - p.y,
                            2.f * acc.z - p.z, 2.f * acc.w - p.w);
    ((int2*)tnext)[idx] = pack4(tn.x, tn.y, tn.z, tn.w);
    float ck = g_coeff[layer][k];
    float4 o = unpack4(((int2*)outb)[idx]);
    ((int2*)outb)[idx] = pack4(o.x + ck * tn.x, o.y + ck * tn.y,
                               o.z + ck * tn.z, o.w + ck * tn.w);
}

// last step: h_out = relu(out + c_k*(2*L~ t_cur - t_prev) + bias)   (fp32 output)
__global__ __launch_bounds__(256) void cheb_last_kernel(const __half* __restrict__ tcur,
                                                        const __half* __restrict__ tprev,
                                                        const __half* __restrict__ outb,
                                                        const float* __restrict__ bias,
                                                        float* __restrict__ hout,
                                                        int layer, int k) {
    int lane = threadIdx.x & 31;
    int half_id = lane >> 4;
    int sub = lane & 15;
    int row = blockIdx.x * 16 + ((threadIdx.x >> 5) << 1) + half_id;
    if (row >= NN) return;
    unsigned mask = 0xFFFFu << (half_id << 4);
    int s = g_rowptr[row], e = g_rowptr[row + 1];
    float4 acc = prop_row4((const int2*)tcur, s, e, sub, mask);
    size_t idx = (size_t)row * 16 + sub;
    float4 p = unpack4(((const int2*)tprev)[idx]);
    float4 tn = make_float4(2.f * acc.x - p.x, 2.f * acc.y - p.y,
                            2.f * acc.z - p.z, 2.f * acc.w - p.w);
    float ck = g_coeff[layer][k];
    float4 o = unpack4(((const int2*)outb)[idx]);
    float4 b = *(const float4*)(bias + sub * 4);
    float4 r;
    r.x = fmaxf(o.x + ck * tn.x + b.x, 0.f);
    r.y = fmaxf(o.y + ck * tn.y + b.y, 0.f);
    r.z = fmaxf(o.z + ck * tn.z + b.z, 0.f);
    r.w = fmaxf(o.w + ck * tn.w + b.w, 0.f);
    *(float4*)(hout + (size_t)row * HID + sub * 4) = r;
}

// ---------------- pool + head + log_softmax ----------------
__global__ __launch_bounds__(256) void pool_head_kernel(const float* __restrict__ h,
                                                        const int* __restrict__ batch,
                                                        const float* __restrict__ lin1w,
                                                        const float* __restrict__ lin1b,
                                                        const float* __restrict__ lin2w,
                                                        const float* __restrict__ lin2b,
                                                        float* __restrict__ out) {
    int g = blockIdx.x;
    int tid = threadIdx.x;
    int lo = 0, hi = NN;
    while (lo < hi) { int m = (lo + hi) >> 1; if (batch[m] < g) lo = m + 1; else hi = m; }
    int start = lo;
    lo = start; hi = NN;
    while (lo < hi) { int m = (lo + hi) >> 1; if (batch[m] < g + 1) lo = m + 1; else hi = m; }
    int end = lo;

    int f = tid & 63, sub = tid >> 6;
    float acc = 0.f;
    for (int i = start + sub; i < end; i += 4) acc += h[(size_t)i * HID + f];
    __shared__ float red[4][64];
    red[sub][f] = acc;
    __syncthreads();
    __shared__ float pooled[64];
    if (tid < 64) {
        float s = red[0][tid] + red[1][tid] + red[2][tid] + red[3][tid];
        float cnt = (float)(end - start);
        pooled[tid] = s / fmaxf(cnt, 1.0f);
    }
    __syncthreads();
    __shared__ float g1[64];
    if (tid < 64) {
        float a = lin1b[tid];
        for (int fk = 0; fk < 64; fk++) a += pooled[fk] * lin1w[fk * 64 + tid];
        g1[tid] = fmaxf(a, 0.f);
    }
    __syncthreads();
    __shared__ float logits[NCLS];
    if (tid < NCLS) {
        float a = lin2b[tid];
        for (int fk = 0; fk < 64; fk++) a += g1[fk] * lin2w[fk * NCLS + tid];
        logits[tid] = a;
    }
    __syncthreads();
    __shared__ float s_lse;
    if (tid == 0) {
        float mx = logits[0];
        for (int c = 1; c < NCLS; c++) mx = fmaxf(mx, logits[c]);
        float s = 0.f;
        for (int c = 0; c < NCLS; c++) s += expf(logits[c] - mx);
        s_lse = mx + logf(s);
    }
    __syncthreads();
    if (tid < NCLS) out[g * NCLS + tid] = logits[tid] - s_lse;
}

// ---------------- host orchestration ----------------
static void spectral_layer(const float* hin, int fin, int layer,
                           const float* W, const float* bias,
                           __half* p_yh, __half* p_t1h, __half* p_t2h,
                           __half* p_outh, float* hout) {
    const int CHEB_GRID = (NN + 15) / 16;
    if (fin == 128)
        gemm_kernel<128><<<(NN + 63) / 64, 256>>>(hin, W, p_yh);
    else
        gemm_kernel<64><<<(NN + 63) / 64, 256>>>(hin, W, p_yh);
    cheb_first_kernel<<<CHEB_GRID, 256>>>(p_yh, p_t1h, p_outh, layer);
    __half* tp = p_yh; __half* tc = p_t1h; __half* tn = p_t2h;
    for (int k = 2; k <= KORD - 2; k++) {
        cheb_step_kernel<<<CHEB_GRID, 256>>>(tc, tp, tn, p_outh, layer, k);
        __half* tmp = tp; tp = tc; tc = tn; tn = tmp;
    }
    cheb_last_kernel<<<CHEB_GRID, 256>>>(tc, tp, p_outh, bias, hout, layer, KORD - 1);
}

extern "C" void kernel_launch(void* const* d_in, const int* in_sizes, int n_in,
                              void* d_out, int out_size) {
    const float* x      = (const float*)d_in[0];
    const int*   ei     = (const int*)d_in[1];
    const int*   batch  = (const int*)d_in[2];
    const float* W1     = (const float*)d_in[3];
    const float* theta1 = (const float*)d_in[4];
    const float* b1     = (const float*)d_in[5];
    const float* Ws     = (const float*)d_in[6];
    const float* thetas = (const float*)d_in[7];
    const float* bs     = (const float*)d_in[8];
    const float* lin1w  = (const float*)d_in[9];
    const float* lin1b  = (const float*)d_in[10];
    const float* lin2w  = (const float*)d_in[11];
    const float* lin2b  = (const float*)d_in[12];
    float* out = (float*)d_out;

    const int* row = ei;
    const int* col = ei + EE;

    void *pv;
    __half *p_yh, *p_t1h, *p_t2h, *p_outh;
    float *p_h;
    int *p_deg, *p_cur;
    cudaGetSymbolAddress(&pv, g_yh);   p_yh  = (__half*)pv;
    cudaGetSymbolAddress(&pv, g_t1h);  p_t1h = (__half*)pv;
    cudaGetSymbolAddress(&pv, g_t2h);  p_t2h = (__half*)pv;
    cudaGetSymbolAddress(&pv, g_outh); p_outh = (__half*)pv;
    cudaGetSymbolAddress(&pv, g_h);    p_h   = (float*)pv;
    cudaGetSymbolAddress(&pv, g_deg);  p_deg = (int*)pv;
    cudaGetSymbolAddress(&pv, g_cursor); p_cur = (int*)pv;

    // ---- CSR build with edge weights ----
    cudaMemsetAsync(p_deg, 0, NN * sizeof(int));
    count_deg_kernel<<<(EE + 255) / 256, 256>>>(row);
    dinv_kernel<<<(NN + 255) / 256, 256>>>();
    scan_kernel<<<1, 1024>>>();
    cudaMemsetAsync(p_cur, 0, NN * sizeof(int));
    scatter_kernel<<<(EE + 255) / 256, 256>>>(row, col);
    coeff_kernel<<<1, 64>>>(theta1, thetas);

    // ---- 3 spectral layers ----
    spectral_layer(x,   128, 0, W1,           b1,       p_yh, p_t1h, p_t2h, p_outh, p_h);
    spectral_layer(p_h,  64, 1, Ws,           bs,       p_yh, p_t1h, p_t2h, p_outh, p_h);
    spectral_layer(p_h,  64, 2, Ws + 64 * 64, bs + HID, p_yh, p_t1h, p_t2h, p_outh, p_h);

    // ---- pool + head ----
    pool_head_kernel<<<NGRAPH, 256>>>(p_h, batch, lin1w, lin1b, lin2w, lin2b, out);
}

// round 4
// speedup vs baseline: 1.2239x; 1.0542x over previous
#include <cuda_runtime.h>
#include <cuda_fp16.h>
#include <math.h>

#define NN 100000
#define EE 1600000
#define HID 64
#define KORD 14
#define HEADS 8
#define NGRAPH 128
#define NCLS 10

// ---------------- scratch (device globals; no runtime alloc) ----------------
__device__ __half g_yh  [NN * HID];
__device__ __half g_t1h [NN * HID];
__device__ __half g_t2h [NN * HID];
__device__ __half g_outh[NN * HID];
__device__ float  g_h   [NN * HID];
__device__ int    g_deg[NN];
__device__ float  g_dinv[NN];
__device__ int    g_rowptr[NN + 1];
__device__ int    g_cursor[NN];
__device__ int2   g_edge[EE];         // {col, float_bits(weight)}
__device__ float  g_coeff[3][KORD];

// ---------------- init: zero deg + cursor ----------------
__global__ void init_kernel() {
    int i = blockIdx.x * blockDim.x + threadIdx.x;
    if (i < NN) { g_deg[i] = 0; g_cursor[i] = 0; }
}

__global__ void count_deg_kernel(const int* __restrict__ row) {
    int e = blockIdx.x * blockDim.x + threadIdx.x;
    if (e < EE) atomicAdd(&g_deg[row[e]], 1);
}

// scan + dinv + coeff fused (single block)
__global__ void scan_kernel(const float* __restrict__ theta1,
                            const float* __restrict__ thetas) {
    __shared__ int sums[1024];
    const int T = 1024;
    int tid = threadIdx.x;

    if (tid < 3 * KORD) {            // coeff = mean over heads, all layers
        int layer = tid / KORD, k = tid % KORD;
        const float* th = (layer == 0) ? theta1 : thetas + (layer - 1) * HEADS * KORD;
        float s = 0.f;
        for (int h = 0; h < HEADS; h++) s += th[h * KORD + k];
        g_coeff[layer][k] = s * (1.0f / HEADS);
    }

    int per = (NN + T - 1) / T;
    int start = tid * per;
    int end = start + per; if (end > NN) end = NN;
    int local = 0;
    for (int i = start; i < end; i++) local += g_deg[i];
    sums[tid] = local;
    __syncthreads();
    for (int off = 1; off < T; off <<= 1) {
        int t = (tid >= off) ? sums[tid - off] : 0;
        __syncthreads();
        sums[tid] += t;
        __syncthreads();
    }
    int excl = sums[tid] - local;
    int run = excl;
    for (int i = start; i < end; i++) {
        int d = g_deg[i];
        g_rowptr[i] = run; run += d;
        g_dinv[i] = rsqrtf(fmaxf((float)d, 1.0f));
    }
    if (tid == T - 1) g_rowptr[NN] = run;
}

__global__ void scatter_kernel(const int* __restrict__ row, const int* __restrict__ col) {
    int e = blockIdx.x * blockDim.x + threadIdx.x;
    if (e < EE) {
        int r = row[e], c = col[e];
        int pos = g_rowptr[r] + atomicAdd(&g_cursor[r], 1);
        float w = -g_dinv[r] * g_dinv[c];   // fold sign of L~ = -D^-1/2 A D^-1/2
        g_edge[pos] = make_int2(c, __float_as_int(w));
    }
}

// ---------------- GEMM: Yh[N][64] = A[N][FIN] @ W[FIN][64]  (half output) ----------------
template <int FIN>
__global__ __launch_bounds__(256) void gemm_kernel(const float* __restrict__ A,
                                                   const float* __restrict__ W,
                                                   __half* __restrict__ Yh) {
    __shared__ float As[64][68];
    __shared__ float Ws[64][64];
    int rowbase = blockIdx.x * 64;
    int tid = threadIdx.x;
    int tx = tid & 15;
    int ty = tid >> 4;
    float acc[4][4];
#pragma unroll
    for (int i = 0; i < 4; i++)
#pragma unroll
        for (int j = 0; j < 4; j++) acc[i][j] = 0.f;

    for (int kk = 0; kk < FIN; kk += 64) {
#pragma unroll
        for (int j = 0; j < 4; j++) {
            int idx = tid + j * 256;
            int r = idx >> 4;
            int kq = idx & 15;
            float4 v = make_float4(0.f, 0.f, 0.f, 0.f);
            int gr = rowbase + r;
            if (gr < NN) v = *(const float4*)(A + (size_t)gr * FIN + kk + kq * 4);
            As[kq * 4 + 0][r] = v.x;
            As[kq * 4 + 1][r] = v.y;
            As[kq * 4 + 2][r] = v.z;
            As[kq * 4 + 3][r] = v.w;
        }
#pragma unroll
        for (int j = 0; j < 4; j++) {
            int idx = tid + j * 256;
            int k = idx >> 4;
            int fq = idx & 15;
            *(float4*)&Ws[k][fq * 4] = *(const float4*)(W + (size_t)(kk + k) * 64 + fq * 4);
        }
        __syncthreads();
#pragma unroll
        for (int k = 0; k < 64; k++) {
            float4 a = *(const float4*)&As[k][ty * 4];
            float4 b = *(const float4*)&Ws[k][tx * 4];
            float ar[4] = {a.x, a.y, a.z, a.w};
            float br[4] = {b.x, b.y, b.z, b.w};
#pragma unroll
            for (int i = 0; i < 4; i++)
#pragma unroll
                for (int j = 0; j < 4; j++) acc[i][j] += ar[i] * br[j];
        }
        __syncthreads();
    }
#pragma unroll
    for (int i = 0; i < 4; i++) {
        int r = rowbase + ty * 4 + i;
        if (r < NN) {
            __half2* dst = (__half2*)(Yh + (size_t)r * HID + tx * 4);
            dst[0] = __floats2half2_rn(acc[i][0], acc[i][1]);
            dst[1] = __floats2half2_rn(acc[i][2], acc[i][3]);
        }
    }
}

// ---------------- Chebyshev propagation: half-warp per row, 4 features/lane ----------------
// Front-batched: 16 predicated gather LDGs in flight before any accumulation.
__device__ __forceinline__ float4 prop_row4(const int2* __restrict__ t,
                                            int s, int e, int sub, unsigned mask) {
    float ax = 0.f, ay = 0.f, az = 0.f, aw = 0.f;
    const int2* tp = t + sub;
    for (int base = s; base < e; base += 16) {
        int idx = base + sub;
        int2 ew = make_int2(0, 0);
        if (idx < e) ew = __ldg(&g_edge[idx]);
        int cnt = e - base;                      // may exceed 16; clamp via j<cnt checks
        int2 raw[16];
        // hoist shuffles + front-batch gathers (predicated, zero-init)
#pragma unroll
        for (int j = 0; j < 16; j++) {
            int cj = __shfl_sync(mask, ew.x, j, 16);
            raw[j] = make_int2(0, 0);
            if (j < cnt) raw[j] = __ldg(&tp[(size_t)cj * 16]);
        }
#pragma unroll
        for (int j = 0; j < 16; j++) {
            float wj = __int_as_float(__shfl_sync(mask, ew.y, j, 16));
            float2 f0 = __half22float2(*(__half2*)&raw[j].x);
            float2 f1 = __half22float2(*(__half2*)&raw[j].y);
            ax += wj * f0.x; ay += wj * f0.y;
            az += wj * f1.x; aw += wj * f1.y;
        }
    }
    return make_float4(ax, ay, az, aw);
}

__device__ __forceinline__ int2 pack4(float a, float b, float c, float d) {
    __half2 h0 = __floats2half2_rn(a, b);
    __half2 h1 = __floats2half2_rn(c, d);
    int2 r;
    r.x = *(int*)&h0;
    r.y = *(int*)&h1;
    return r;
}

__device__ __forceinline__ float4 unpack4(int2 raw) {
    float2 f0 = __half22float2(*(__half2*)&raw.x);
    float2 f1 = __half22float2(*(__half2*)&raw.y);
    return make_float4(f0.x, f0.y, f1.x, f1.y);
}

// first: t_cur = L~ y ; out = c0*y + c1*t_cur
__global__ __launch_bounds__(256) void cheb_first_kernel(const __half* __restrict__ yh,
                                                         __half* __restrict__ tcur,
                                                         __half* __restrict__ outb,
                                                         int layer) {
    int lane = threadIdx.x & 31;
    int half_id = lane >> 4;
    int sub = lane & 15;
    int row = blockIdx.x * 16 + ((threadIdx.x >> 5) << 1) + half_id;
    if (row >= NN) return;
    unsigned mask = 0xFFFFu << (half_id << 4);
    int s = g_rowptr[row], e = g_rowptr[row + 1];
    float4 acc = prop_row4((const int2*)yh, s, e, sub, mask);
    float c0 = g_coeff[layer][0], c1 = g_coeff[layer][1];
    size_t idx = (size_t)row * 16 + sub;
    float4 yv = unpack4(((const int2*)yh)[idx]);
    ((int2*)tcur)[idx] = pack4(acc.x, acc.y, acc.z, acc.w);
    ((int2*)outb)[idx] = pack4(c0 * yv.x + c1 * acc.x, c0 * yv.y + c1 * acc.y,
                               c0 * yv.z + c1 * acc.z, c0 * yv.w + c1 * acc.w);
}

// step k: t_next = 2*L~ t_cur - t_prev ; out += c_k * t_next
__global__ __launch_bounds__(256) void cheb_step_kernel(const __half* __restrict__ tcur,
                                                        const __half* __restrict__ tprev,
                                                        __half* __restrict__ tnext,
                                                        __half* __restrict__ outb,
                                                        int layer, int k) {
    int lane = threadIdx.x & 31;
    int half_id = lane >> 4;
    int sub = lane & 15;
    int row = blockIdx.x * 16 + ((threadIdx.x >> 5) << 1) + half_id;
    if (row >= NN) return;
    unsigned mask = 0xFFFFu << (half_id << 4);
    int s = g_rowptr[row], e = g_rowptr[row + 1];
    float4 acc = prop_row4((const int2*)tcur, s, e, sub, mask);
    size_t idx = (size_t)row * 16 + sub;
    float4 p = unpack4(((const int2*)tprev)[idx]);
    float4 tn = make_float4(2.f * acc.x - p.x, 2.f * acc.y - p.y,
                            2.f * acc.z - p.z, 2.f * acc.w - p.w);
    ((int2*)tnext)[idx] = pack4(tn.x, tn.y, tn.z, tn.w);
    float ck = g_coeff[layer][k];
    float4 o = unpack4(((int2*)outb)[idx]);
    ((int2*)outb)[idx] = pack4(o.x + ck * tn.x, o.y + ck * tn.y,
                               o.z + ck * tn.z, o.w + ck * tn.w);
}

// last step: h_out = relu(out + c_k*(2*L~ t_cur - t_prev) + bias)   (fp32 output)
__global__ __launch_bounds__(256) void cheb_last_kernel(const __half* __restrict__ tcur,
                                                        const __half* __restrict__ tprev,
                                                        const __half* __restrict__ outb,
                                                        const float* __restrict__ bias,
                                                        float* __restrict__ hout,
                                                        int layer, int k) {
    int lane = threadIdx.x & 31;
    int half_id = lane >> 4;
    int sub = lane & 15;
    int row = blockIdx.x * 16 + ((threadIdx.x >> 5) << 1) + half_id;
    if (row >= NN) return;
    unsigned mask = 0xFFFFu << (half_id << 4);
    int s = g_rowptr[row], e = g_rowptr[row + 1];
    float4 acc = prop_row4((const int2*)tcur, s, e, sub, mask);
    size_t idx = (size_t)row * 16 + sub;
    float4 p = unpack4(((const int2*)tprev)[idx]);
    float4 tn = make_float4(2.f * acc.x - p.x, 2.f * acc.y - p.y,
                            2.f * acc.z - p.z, 2.f * acc.w - p.w);
    float ck = g_coeff[layer][k];
    float4 o = unpack4(((const int2*)outb)[idx]);
    float4 b = *(const float4*)(bias + sub * 4);
    float4 r;
    r.x = fmaxf(o.x + ck * tn.x + b.x, 0.f);
    r.y = fmaxf(o.y + ck * tn.y + b.y, 0.f);
    r.z = fmaxf(o.z + ck * tn.z + b.z, 0.f);
    r.w = fmaxf(o.w + ck * tn.w + b.w, 0.f);
    *(float4*)(hout + (size_t)row * HID + sub * 4) = r;
}

// ---------------- pool + head + log_softmax ----------------
__global__ __launch_bounds__(256) void pool_head_kernel(const float* __restrict__ h,
                                                        const int* __restrict__ batch,
                                                        const float* __restrict__ lin1w,
                                                        const float* __restrict__ lin1b,
                                                        const float* __restrict__ lin2w,
                                                        const float* __restrict__ lin2b,
                                                        float* __restrict__ out) {
    int g = blockIdx.x;
    int tid = threadIdx.x;
    int lo = 0, hi = NN;
    while (lo < hi) { int m = (lo + hi) >> 1; if (batch[m] < g) lo = m + 1; else hi = m; }
    int start = lo;
    lo = start; hi = NN;
    while (lo < hi) { int m = (lo + hi) >> 1; if (batch[m] < g + 1) lo = m + 1; else hi = m; }
    int end = lo;

    int f = tid & 63, sub = tid >> 6;
    float acc = 0.f;
    for (int i = start + sub; i < end; i += 4) acc += h[(size_t)i * HID + f];
    __shared__ float red[4][64];
    red[sub][f] = acc;
    __syncthreads();
    __shared__ float pooled[64];
    if (tid < 64) {
        float s = red[0][tid] + red[1][tid] + red[2][tid] + red[3][tid];
        float cnt = (float)(end - start);
        pooled[tid] = s / fmaxf(cnt, 1.0f);
    }
    __syncthreads();
    __shared__ float g1[64];
    if (tid < 64) {
        float a = lin1b[tid];
        for (int fk = 0; fk < 64; fk++) a += pooled[fk] * lin1w[fk * 64 + tid];
        g1[tid] = fmaxf(a, 0.f);
    }
    __syncthreads();
    __shared__ float logits[NCLS];
    if (tid < NCLS) {
        float a = lin2b[tid];
        for (int fk = 0; fk < 64; fk++) a += g1[fk] * lin2w[fk * NCLS + tid];
        logits[tid] = a;
    }
    __syncthreads();
    __shared__ float s_lse;
    if (tid == 0) {
        float mx = logits[0];
        for (int c = 1; c < NCLS; c++) mx = fmaxf(mx, logits[c]);
        float s = 0.f;
        for (int c = 0; c < NCLS; c++) s += expf(logits[c] - mx);
        s_lse = mx + logf(s);
    }
    __syncthreads();
    if (tid < NCLS) out[g * NCLS + tid] = logits[tid] - s_lse;
}

// ---------------- host orchestration ----------------
static void spectral_layer(const float* hin, int fin, int layer,
                           const float* W, const float* bias,
                           __half* p_yh, __half* p_t1h, __half* p_t2h,
                           __half* p_outh, float* hout) {
    const int CHEB_GRID = (NN + 15) / 16;
    if (fin == 128)
        gemm_kernel<128><<<(NN + 63) / 64, 256>>>(hin, W, p_yh);
    else
        gemm_kernel<64><<<(NN + 63) / 64, 256>>>(hin, W, p_yh);
    cheb_first_kernel<<<CHEB_GRID, 256>>>(p_yh, p_t1h, p_outh, layer);
    __half* tp = p_yh; __half* tc = p_t1h; __half* tn = p_t2h;
    for (int k = 2; k <= KORD - 2; k++) {
        cheb_step_kernel<<<CHEB_GRID, 256>>>(tc, tp, tn, p_outh, layer, k);
        __half* tmp = tp; tp = tc; tc = tn; tn = tmp;
    }
    cheb_last_kernel<<<CHEB_GRID, 256>>>(tc, tp, p_outh, bias, hout, layer, KORD - 1);
}

extern "C" void kernel_launch(void* const* d_in, const int* in_sizes, int n_in,
                              void* d_out, int out_size) {
    const float* x      = (const float*)d_in[0];
    const int*   ei     = (const int*)d_in[1];
    const int*   batch  = (const int*)d_in[2];
    const float* W1     = (const float*)d_in[3];
    const float* theta1 = (const float*)d_in[4];
    const float* b1     = (const float*)d_in[5];
    const float* Ws     = (const float*)d_in[6];
    const float* thetas = (const float*)d_in[7];
    const float* bs     = (const float*)d_in[8];
    const float* lin1w  = (const float*)d_in[9];
    const float* lin1b  = (const float*)d_in[10];
    const float* lin2w  = (const float*)d_in[11];
    const float* lin2b  = (const float*)d_in[12];
    float* out = (float*)d_out;

    const int* row = ei;
    const int* col = ei + EE;

    void *pv;
    __half *p_yh, *p_t1h, *p_t2h, *p_outh;
    float *p_h;
    cudaGetSymbolAddress(&pv, g_yh);   p_yh  = (__half*)pv;
    cudaGetSymbolAddress(&pv, g_t1h);  p_t1h = (__half*)pv;
    cudaGetSymbolAddress(&pv, g_t2h);  p_t2h = (__half*)pv;
    cudaGetSymbolAddress(&pv, g_outh); p_outh = (__half*)pv;
    cudaGetSymbolAddress(&pv, g_h);    p_h   = (float*)pv;

    // ---- CSR build (4 launches so launch #6 = cheb_first for ncu -s 5) ----
    init_kernel<<<(NN + 255) / 256, 256>>>();
    count_deg_kernel<<<(EE + 255) / 256, 256>>>(row);
    scan_kernel<<<1, 1024>>>(theta1, thetas);
    scatter_kernel<<<(EE + 255) / 256, 256>>>(row, col);

    // ---- 3 spectral layers ----
    spectral_layer(x,   128, 0, W1,           b1,       p_yh, p_t1h, p_t2h, p_outh, p_h);
    spectral_layer(p_h,  64, 1, Ws,           bs,       p_yh, p_t1h, p_t2h, p_outh, p_h);
    spectral_layer(p_h,  64, 2, Ws + 64 * 64, bs + HID, p_yh, p_t1h, p_t2h, p_outh, p_h);

    // ---- pool + head ----
    pool_head_kernel<<<NGRAPH, 256>>>(p_h, batch, lin1w, lin1b, lin2w, lin2b, out);
}